// round 8
// baseline (speedup 1.0000x reference)
#include <cuda_runtime.h>
#include <math.h>

#define NB 8
#define M1N 2000
#define M2N 400
#define ATN 2400
#define NN (NB*ATN)
#define HD 64
#define NGN 50
#define LN 4
#define CN 4
#define E1N 60000
#define E2N 20000
#define E3N 20000
#define ETN 100000

typedef unsigned long long u64;

__device__ float g_h[NN*HD];
__device__ float g_x[3][NN*HD];
__device__ float g_agg[3][NN*HD];
__device__ float g_W[LN*ETN*HD];
__device__ float g_attr[ETN*NGN];
__device__ float g_ccut[ETN];
__device__ int   g_csrsrc[ETN];
__device__ int   g_csrw[ETN];
__device__ int   g_cnt[3*ATN];    // zero-init; re-zeroed by k_cleanup each run
__device__ int   g_cur[3*ATN];
__device__ int   g_rs[3*(ATN+1)];
__device__ int   g_cc[3*CN];
__device__ int   g_ccur[3*CN];
__device__ int   g_cbase[3*(CN+1)];

__device__ __forceinline__ float sspf(float x){
    return fmaxf(x, 0.0f) + log1pf(__expf(-fabsf(x))) - 0.6931471805599453f;
}

__device__ __forceinline__ void fma2(u64& d, u64 a, u64 b){
    asm("fma.rn.f32x2 %0, %1, %2, %0;" : "+l"(d) : "l"(a), "l"(b));
}

__device__ __forceinline__ void resolve_edge(int idx, int& g, int& e, int& eofs){
    if(idx < E1N){ g = 0; e = idx; eofs = 0; }
    else if(idx < E1N+E2N){ g = 1; e = idx-E1N; eofs = E1N; }
    else { g = 2; e = idx-E1N-E2N; eofs = E1N+E2N; }
}

// ---------------- preprocessing ----------------
__global__ void k_count(const int* __restrict__ e1, const int* __restrict__ e2,
                        const int* __restrict__ e3,
                        const int* __restrict__ c1, const int* __restrict__ c2,
                        const int* __restrict__ c3){
    int idx = blockIdx.x*blockDim.x + threadIdx.x;
    if(idx >= ETN) return;
    int g, e, eofs; resolve_edge(idx, g, e, eofs);
    const int* cp  = (g==0) ? c1 : ((g==1) ? c2 : c3);
    const int* eip = (g==0) ? e1 : ((g==1) ? e2 : e3);
    atomicAdd(&g_cc[g*CN + cp[e]], 1);
    atomicAdd(&g_cnt[g*ATN + eip[2*e + 1]], 1);
}

__global__ void k_cbase_rs(){
    int g = blockIdx.x;
    int lane = threadIdx.x;
    if(lane == 0){
        int s = 0;
        g_cbase[g*(CN+1)] = 0;
        for(int c = 0; c < CN; c++){ s += g_cc[g*CN + c]; g_cbase[g*(CN+1)+c+1] = s; }
    }
    const int per = ATN / 32;
    int base = lane * per;
    int sum = 0;
    for(int i = 0; i < per; i++) sum += g_cnt[g*ATN + base + i];
    int incl = sum;
    #pragma unroll
    for(int o = 1; o < 32; o <<= 1){
        int v = __shfl_up_sync(0xFFFFFFFFu, incl, o);
        if(lane >= o) incl += v;
    }
    int run = incl - sum;
    for(int i = 0; i < per; i++){
        g_rs[g*(ATN+1) + base + i] = run;
        run += g_cnt[g*ATN + base + i];
    }
    if(lane == 31) g_rs[g*(ATN+1) + ATN] = run;
}

__global__ void k_fill(const int* __restrict__ e1, const int* __restrict__ e2,
                       const int* __restrict__ e3,
                       const float* __restrict__ w1, const float* __restrict__ w2,
                       const float* __restrict__ w3,
                       const int* __restrict__ c1, const int* __restrict__ c2,
                       const int* __restrict__ c3){
    int idx = blockIdx.x*blockDim.x + threadIdx.x;
    if(idx >= ETN) return;
    int g, e, eofs; resolve_edge(idx, g, e, eofs);
    const int* cp  = (g==0) ? c1 : ((g==1) ? c2 : c3);
    const int* eip = (g==0) ? e1 : ((g==1) ? e2 : e3);
    const float* wp = (g==0) ? w1 : ((g==1) ? w2 : w3);
    int col = cp[e];
    float d = wp[e];
    int p = g_cbase[g*(CN+1)+col] + atomicAdd(&g_ccur[g*CN+col], 1);
    g_ccut[eofs + p] = 0.5f * (cosf(d * 3.14159265358979323846f / 10.0f) + 1.0f);
    const float step = 10.0f / 49.0f;
    const float coeff = -0.5f / (step*step);
    float* ap = &g_attr[(size_t)(eofs + p)*NGN];
    #pragma unroll 10
    for(int k = 0; k < NGN; k++){
        float tt = d - step * (float)k;
        ap[k] = __expf(coeff * tt * tt);
    }
    int src = eip[2*e], dst = eip[2*e + 1];
    int pc = g_rs[g*(ATN+1) + dst] + atomicAdd(&g_cur[g*ATN + dst], 1);
    g_csrsrc[eofs + pc] = src;
    g_csrw[eofs + pc] = p;
}

__global__ void k_embed(const int* __restrict__ sites, const int* __restrict__ sitesp,
                        const float* __restrict__ embw, const float* __restrict__ embpw){
    int idx = blockIdx.x*blockDim.x + threadIdx.x;
    if(idx >= NN*HD) return;
    int n = idx >> 6, f = idx & 63;
    int b = n / ATN, i = n - b*ATN;
    float v;
    if(i < M1N) v = embw[sites[b*M1N + i]*HD + f];
    else        v = embpw[sitesp[b*M2N + (i - M1N)]*HD + f];
    g_h[idx] = v;
}

__global__ void k_cleanup(){
    int i = blockIdx.x*blockDim.x + threadIdx.x;
    if(i < 3*ATN){ g_cnt[i] = 0; g_cur[i] = 0; }
    if(i < 3*CN){ g_cc[i] = 0; g_ccur[i] = 0; }
}

// ---------------- edge-filter MLP: 64x64 tile, 128 thr, 8x4/thread ----------------
// union buffer for A-tile/H-tile: smem 33KB -> 6 CTAs/SM
__global__ void k_wmlp(const float* __restrict__ mw1, const float* __restrict__ mb1,
                       const float* __restrict__ mw2, const float* __restrict__ mb2,
                       int g, int eofs){
    const int c = blockIdx.y, l = blockIdx.z;
    const int cb = g_cbase[g*(CN+1)+c];
    const int ce = g_cbase[g*(CN+1)+c+1];
    const int r0 = cb + blockIdx.x*64;
    if(r0 >= ce) return;
    const int t = threadIdx.x;
    const int tc = t & 15, tr = t >> 4;

    __shared__ __align__(16) float sW[64*64];
    __shared__ __align__(16) float sU[64*65];   // attr tile, then H tile

    const int pgc = (l*3 + g)*CN + c;
    const float* w1 = mw1 + pgc*NGN*HD;
    for(int i = t; i < NGN*HD; i += 128) sW[i] = w1[i];
    for(int i = t; i < 64*NGN; i += 128){
        int rr = i / NGN, kk = i - rr*NGN;
        int row = r0 + rr;
        sU[rr*65 + kk] = (row < ce) ? g_attr[(size_t)(eofs + row)*NGN + kk] : 0.0f;
    }
    __syncthreads();

    float acc[8][4];
    #pragma unroll
    for(int ri = 0; ri < 8; ri++){ acc[ri][0]=0; acc[ri][1]=0; acc[ri][2]=0; acc[ri][3]=0; }
    for(int k = 0; k < NGN; k++){
        float4 w = *(const float4*)&sW[k*64 + tc*4];
        #pragma unroll
        for(int ri = 0; ri < 8; ri++){
            float a = sU[(tr*8 + ri)*65 + k];
            acc[ri][0] += a*w.x; acc[ri][1] += a*w.y;
            acc[ri][2] += a*w.z; acc[ri][3] += a*w.w;
        }
    }
    __syncthreads();      // all reads of sU (attr) and sW (w1) done

    float b1v[4];
    #pragma unroll
    for(int j = 0; j < 4; j++) b1v[j] = mb1[pgc*HD + tc*4 + j];
    #pragma unroll
    for(int ri = 0; ri < 8; ri++)
        #pragma unroll
        for(int j = 0; j < 4; j++)
            sU[(tr*8 + ri)*65 + tc*4 + j] = sspf(acc[ri][j] + b1v[j]);
    const float* w2 = mw2 + pgc*HD*HD;
    for(int i = t; i < HD*HD; i += 128) sW[i] = w2[i];
    __syncthreads();

    float acc2[8][4];
    #pragma unroll
    for(int ri = 0; ri < 8; ri++){ acc2[ri][0]=0; acc2[ri][1]=0; acc2[ri][2]=0; acc2[ri][3]=0; }
    for(int k = 0; k < HD; k++){
        float4 w = *(const float4*)&sW[k*64 + tc*4];
        #pragma unroll
        for(int ri = 0; ri < 8; ri++){
            float a = sU[(tr*8 + ri)*65 + k];
            acc2[ri][0] += a*w.x; acc2[ri][1] += a*w.y;
            acc2[ri][2] += a*w.z; acc2[ri][3] += a*w.w;
        }
    }
    float b2v[4];
    #pragma unroll
    for(int j = 0; j < 4; j++) b2v[j] = mb2[pgc*HD + tc*4 + j];
    #pragma unroll
    for(int ri = 0; ri < 8; ri++){
        int row = r0 + tr*8 + ri;
        if(row < ce){
            float cc = g_ccut[eofs + row];
            float4 o;
            o.x = (acc2[ri][0] + b2v[0]) * cc;
            o.y = (acc2[ri][1] + b2v[1]) * cc;
            o.z = (acc2[ri][2] + b2v[2]) * cc;
            o.w = (acc2[ri][3] + b2v[3]) * cc;
            *(float4*)&g_W[(size_t)(l*ETN + eofs + row)*HD + tc*4] = o;
        }
    }
}

// ---------------- lin1: 64-row tile, fused over 3 graphs (h loaded once) ----------------
__global__ void k_lin1(const float* __restrict__ cw1, int l){
    const int r0 = blockIdx.x * 64;
    const int t = threadIdx.x, tc = t & 15, tr = t >> 4;
    __shared__ __align__(16) float sW[64*64];
    __shared__ float sHt[64*65];
    for(int i = t; i < 64*64; i += 128){
        int rr = i >> 6, kk = i & 63;
        sHt[rr*65 + kk] = g_h[(r0 + rr)*HD + kk];
    }
    for(int g = 0; g < 3; g++){
        const float* w = cw1 + (l*3 + g)*HD*HD;
        for(int i = t; i < HD*HD; i += 128) sW[i] = w[i];
        __syncthreads();
        float acc[8][4];
        #pragma unroll
        for(int ri = 0; ri < 8; ri++){ acc[ri][0]=0; acc[ri][1]=0; acc[ri][2]=0; acc[ri][3]=0; }
        for(int k = 0; k < HD; k++){
            float4 w4 = *(const float4*)&sW[k*64 + tc*4];
            #pragma unroll
            for(int ri = 0; ri < 8; ri++){
                float a = sHt[(tr*8 + ri)*65 + k];
                acc[ri][0] += a*w4.x; acc[ri][1] += a*w4.y;
                acc[ri][2] += a*w4.z; acc[ri][3] += a*w4.w;
            }
        }
        float* xo = g_x[g];
        #pragma unroll
        for(int ri = 0; ri < 8; ri++){
            int row = r0 + tr*8 + ri;
            float4 o; o.x = acc[ri][0]; o.y = acc[ri][1]; o.z = acc[ri][2]; o.w = acc[ri][3];
            *(float4*)&xo[row*HD + tc*4] = o;
        }
        __syncthreads();   // all reads of sW done before next graph overwrites
    }
}

// ---------------- CSR aggregation: 1 warp per dst, u64 lanes ----------------
__global__ void k_agg(int l){
    const int gph = blockIdx.y;
    const int t = threadIdx.x;
    const int f2 = t & 31;
    const int dq = t >> 5;
    const int dst = blockIdx.x*8 + dq;
    const int eofs = (gph == 0) ? 0 : ((gph == 1) ? E1N : (E1N + E2N));
    const int s = g_rs[gph*(ATN+1) + dst];
    const int e = g_rs[gph*(ATN+1) + dst + 1];
    const u64* __restrict__ xq = (const u64*)g_x[gph];
    const u64* __restrict__ Wq = (const u64*)(g_W + (size_t)l*ETN*HD) + (size_t)eofs*32;
    u64 acc[NB];
    #pragma unroll
    for(int b = 0; b < NB; b++) acc[b] = 0ull;
    int src = 0, wp = 0;
    if(s < e){ src = __ldg(&g_csrsrc[eofs + s]); wp = __ldg(&g_csrw[eofs + s]); }
    for(int p = s; p < e; p++){
        int ns = 0, nw = 0;
        if(p + 1 < e){ ns = __ldg(&g_csrsrc[eofs + p + 1]); nw = __ldg(&g_csrw[eofs + p + 1]); }
        u64 w = Wq[(size_t)wp*32 + f2];
        int base = src*32 + f2;
        #pragma unroll
        for(int b = 0; b < NB; b++)
            fma2(acc[b], xq[base + b*ATN*32], w);
        src = ns; wp = nw;
    }
    u64* aq = (u64*)g_agg[gph];
    int ob = dst*32 + f2;
    #pragma unroll
    for(int b = 0; b < NB; b++)
        aq[ob + b*ATN*32] = acc[b];
}

// ---------------- block: 64-row tile, union buffer, fused over 3 graphs ----------------
__global__ void k_block(const float* __restrict__ cw2, const float* __restrict__ cb2,
                        const float* __restrict__ bw, const float* __restrict__ bb,
                        int l){
    const int r0 = blockIdx.x * 64;
    const int t = threadIdx.x, tc = t & 15, tr = t >> 4;
    __shared__ __align__(16) float sW[64*64];
    __shared__ __align__(16) float sU[64*65];   // agg tile, then T tile
    float hacc[8][4];
    float bacc[4];
    #pragma unroll
    for(int ri = 0; ri < 8; ri++){ hacc[ri][0]=0; hacc[ri][1]=0; hacc[ri][2]=0; hacc[ri][3]=0; }
    #pragma unroll
    for(int j = 0; j < 4; j++) bacc[j] = 0.0f;

    for(int g = 0; g < 3; g++){
        const float* w = cw2 + (l*3 + g)*HD*HD;
        for(int i = t; i < HD*HD; i += 128) sW[i] = w[i];
        const float* ag = g_agg[g];
        for(int i = t; i < 64*64; i += 128){
            int rr = i >> 6, kk = i & 63;
            sU[rr*65 + kk] = ag[(r0 + rr)*HD + kk];
        }
        __syncthreads();

        float acc[8][4];
        #pragma unroll
        for(int ri = 0; ri < 8; ri++){ acc[ri][0]=0; acc[ri][1]=0; acc[ri][2]=0; acc[ri][3]=0; }
        for(int k = 0; k < HD; k++){
            float4 w4 = *(const float4*)&sW[k*64 + tc*4];
            #pragma unroll
            for(int ri = 0; ri < 8; ri++){
                float a = sU[(tr*8 + ri)*65 + k];
                acc[ri][0] += a*w4.x; acc[ri][1] += a*w4.y;
                acc[ri][2] += a*w4.z; acc[ri][3] += a*w4.w;
            }
        }
        __syncthreads();   // reads of sU (agg) and sW (cw2) done

        float b2v[4];
        #pragma unroll
        for(int j = 0; j < 4; j++) b2v[j] = cb2[(l*3 + g)*HD + tc*4 + j];
        #pragma unroll
        for(int ri = 0; ri < 8; ri++)
            #pragma unroll
            for(int j = 0; j < 4; j++)
                sU[(tr*8 + ri)*65 + tc*4 + j] = sspf(acc[ri][j] + b2v[j]);
        const float* w2 = bw + (l*3 + g)*HD*HD;
        for(int i = t; i < HD*HD; i += 128) sW[i] = w2[i];
        __syncthreads();

        for(int k = 0; k < HD; k++){
            float4 w4 = *(const float4*)&sW[k*64 + tc*4];
            #pragma unroll
            for(int ri = 0; ri < 8; ri++){
                float a = sU[(tr*8 + ri)*65 + k];
                hacc[ri][0] += a*w4.x; hacc[ri][1] += a*w4.y;
                hacc[ri][2] += a*w4.z; hacc[ri][3] += a*w4.w;
            }
        }
        #pragma unroll
        for(int j = 0; j < 4; j++) bacc[j] += bb[(l*3 + g)*HD + tc*4 + j];
        __syncthreads();   // reads done before next graph overwrites sU/sW
    }

    #pragma unroll
    for(int ri = 0; ri < 8; ri++){
        int row = r0 + tr*8 + ri;
        float4* hp = (float4*)&g_h[row*HD + tc*4];
        float4 hv = *hp;
        hv.x += hacc[ri][0] + bacc[0];
        hv.y += hacc[ri][1] + bacc[1];
        hv.z += hacc[ri][2] + bacc[2];
        hv.w += hacc[ri][3] + bacc[3];
        *hp = hv;
    }
}

__global__ void k_readout(const float* __restrict__ ow1, const float* __restrict__ ob1,
                          const float* __restrict__ ow2, const float* __restrict__ ob2,
                          float* __restrict__ out){
    __shared__ float sS[NB*HD];
    __shared__ float sV[NB*32];
    int t = threadIdx.x;
    int b = t >> 6, f = t & 63;
    float s = 0.0f;
    const float* hp = g_h + (size_t)(b*ATN + M1N)*HD + f;
    #pragma unroll 4
    for(int i = 0; i < M2N; i++) s += hp[(size_t)i*HD];
    sS[b*HD + f] = s;
    __syncthreads();
    if(t < NB*32){
        int b2 = t >> 5, j = t & 31;
        float v = 0.0f;
        #pragma unroll 8
        for(int f2 = 0; f2 < HD; f2++) v += sS[b2*HD + f2] * ow1[f2*32 + j];
        sV[b2*32 + j] = v + (float)M2N * ob1[j];
    }
    __syncthreads();
    if(t < NB){
        float o = 0.0f;
        #pragma unroll
        for(int j = 0; j < 32; j++) o += sV[t*32 + j] * ow2[j];
        out[t] = o + (float)M2N * ob2[0];
    }
}

extern "C" void kernel_launch(void* const* d_in, const int* in_sizes, int n_in,
                              void* d_out, int out_size){
    (void)in_sizes; (void)n_in; (void)out_size;
    const int*   sites  = (const int*)d_in[0];
    const int*   sitesp = (const int*)d_in[1];
    const int*   ei1 = (const int*)d_in[2];
    const float* ew1 = (const float*)d_in[3];
    const int*   c1  = (const int*)d_in[4];
    const int*   ei2 = (const int*)d_in[5];
    const float* ew2 = (const float*)d_in[6];
    const int*   c2  = (const int*)d_in[7];
    const int*   ei3 = (const int*)d_in[8];
    const float* ew3 = (const float*)d_in[9];
    const int*   c3  = (const int*)d_in[10];
    const float* embw  = (const float*)d_in[11];
    const float* embpw = (const float*)d_in[12];
    const float* mw1 = (const float*)d_in[13];
    const float* mb1 = (const float*)d_in[14];
    const float* mw2 = (const float*)d_in[15];
    const float* mb2 = (const float*)d_in[16];
    const float* cw1 = (const float*)d_in[17];
    const float* cw2 = (const float*)d_in[18];
    const float* cb2 = (const float*)d_in[19];
    const float* bw  = (const float*)d_in[20];
    const float* bb  = (const float*)d_in[21];
    const float* ow1 = (const float*)d_in[22];
    const float* ob1 = (const float*)d_in[23];
    const float* ow2 = (const float*)d_in[24];
    const float* ob2 = (const float*)d_in[25];
    float* out = (float*)d_out;

    k_count<<<(ETN + 255)/256, 256>>>(ei1, ei2, ei3, c1, c2, c3);               // 1
    k_cbase_rs<<<3, 32>>>();                                                    // 2
    k_fill<<<(ETN + 255)/256, 256>>>(ei1, ei2, ei3, ew1, ew2, ew3, c1, c2, c3); // 3

    dim3 gw0((E1N + 63)/64, CN, LN);
    dim3 gw1((E2N + 63)/64, CN, LN);
    dim3 gw2((E3N + 63)/64, CN, LN);
    k_wmlp<<<gw0, 128>>>(mw1, mb1, mw2, mb2, 0, 0);                             // 4 <- profiled
    k_wmlp<<<gw1, 128>>>(mw1, mb1, mw2, mb2, 1, E1N);
    k_wmlp<<<gw2, 128>>>(mw1, mb1, mw2, mb2, 2, E1N + E2N);
    k_embed<<<(NN*HD + 255)/256, 256>>>(sites, sitesp, embw, embpw);

    for(int l = 0; l < LN; l++){
        k_lin1<<<NN/64, 128>>>(cw1, l);
        k_agg<<<dim3(ATN/8, 3), 256>>>(l);
        k_block<<<NN/64, 128>>>(cw2, cb2, bw, bb, l);
    }
    k_readout<<<1, 512>>>(ow1, ob1, ow2, ob2, out);
    k_cleanup<<<(3*ATN + 255)/256, 256>>>();
}

// round 9
// speedup vs baseline: 1.0779x; 1.0779x over previous
#include <cuda_runtime.h>
#include <math.h>

#define NB 8
#define M1N 2000
#define M2N 400
#define ATN 2400
#define NN (NB*ATN)
#define HD 64
#define NGN 50
#define LN 4
#define CN 4
#define E1N 60000
#define E2N 20000
#define E3N 20000
#define ETN 100000

typedef unsigned long long u64;

__device__ float g_h[NN*HD];
__device__ float g_x[3][NN*HD];
__device__ float g_agg[3][NN*HD];
__device__ float g_W[LN*ETN*HD];
__device__ float g_attr[ETN*NGN];
__device__ float g_ccut[ETN];
__device__ int   g_csrsrc[ETN];
__device__ int   g_csrw[ETN];
__device__ int   g_cnt[3*ATN];    // zero-init; re-zeroed by k_cleanup each run
__device__ int   g_cur[3*ATN];
__device__ int   g_rs[3*(ATN+1)];
__device__ int   g_cc[3*CN];
__device__ int   g_ccur[3*CN];
__device__ int   g_cbase[3*(CN+1)];

__device__ __forceinline__ float sspf(float x){
    return fmaxf(x, 0.0f) + log1pf(__expf(-fabsf(x))) - 0.6931471805599453f;
}

__device__ __forceinline__ void fma2(u64& d, u64 a, u64 b){
    asm("fma.rn.f32x2 %0, %1, %2, %0;" : "+l"(d) : "l"(a), "l"(b));
}

__device__ __forceinline__ void resolve_edge(int idx, int& g, int& e, int& eofs){
    if(idx < E1N){ g = 0; e = idx; eofs = 0; }
    else if(idx < E1N+E2N){ g = 1; e = idx-E1N; eofs = E1N; }
    else { g = 2; e = idx-E1N-E2N; eofs = E1N+E2N; }
}

// ---------------- preprocessing ----------------
__global__ void k_count(const int* __restrict__ e1, const int* __restrict__ e2,
                        const int* __restrict__ e3,
                        const int* __restrict__ c1, const int* __restrict__ c2,
                        const int* __restrict__ c3){
    int idx = blockIdx.x*blockDim.x + threadIdx.x;
    if(idx >= ETN) return;
    int g, e, eofs; resolve_edge(idx, g, e, eofs);
    const int* cp  = (g==0) ? c1 : ((g==1) ? c2 : c3);
    const int* eip = (g==0) ? e1 : ((g==1) ? e2 : e3);
    atomicAdd(&g_cc[g*CN + cp[e]], 1);
    atomicAdd(&g_cnt[g*ATN + eip[2*e + 1]], 1);
}

__global__ void k_cbase_rs(){
    int g = blockIdx.x;
    int lane = threadIdx.x;
    if(lane == 0){
        int s = 0;
        g_cbase[g*(CN+1)] = 0;
        for(int c = 0; c < CN; c++){ s += g_cc[g*CN + c]; g_cbase[g*(CN+1)+c+1] = s; }
    }
    const int per = ATN / 32;
    int base = lane * per;
    int sum = 0;
    for(int i = 0; i < per; i++) sum += g_cnt[g*ATN + base + i];
    int incl = sum;
    #pragma unroll
    for(int o = 1; o < 32; o <<= 1){
        int v = __shfl_up_sync(0xFFFFFFFFu, incl, o);
        if(lane >= o) incl += v;
    }
    int run = incl - sum;
    for(int i = 0; i < per; i++){
        g_rs[g*(ATN+1) + base + i] = run;
        run += g_cnt[g*ATN + base + i];
    }
    if(lane == 31) g_rs[g*(ATN+1) + ATN] = run;
}

__global__ void k_fill(const int* __restrict__ e1, const int* __restrict__ e2,
                       const int* __restrict__ e3,
                       const float* __restrict__ w1, const float* __restrict__ w2,
                       const float* __restrict__ w3,
                       const int* __restrict__ c1, const int* __restrict__ c2,
                       const int* __restrict__ c3){
    int idx = blockIdx.x*blockDim.x + threadIdx.x;
    if(idx >= ETN) return;
    int g, e, eofs; resolve_edge(idx, g, e, eofs);
    const int* cp  = (g==0) ? c1 : ((g==1) ? c2 : c3);
    const int* eip = (g==0) ? e1 : ((g==1) ? e2 : e3);
    const float* wp = (g==0) ? w1 : ((g==1) ? w2 : w3);
    int col = cp[e];
    float d = wp[e];
    int p = g_cbase[g*(CN+1)+col] + atomicAdd(&g_ccur[g*CN+col], 1);
    g_ccut[eofs + p] = 0.5f * (cosf(d * 3.14159265358979323846f / 10.0f) + 1.0f);
    const float step = 10.0f / 49.0f;
    const float coeff = -0.5f / (step*step);
    float* ap = &g_attr[(size_t)(eofs + p)*NGN];
    #pragma unroll 10
    for(int k = 0; k < NGN; k++){
        float tt = d - step * (float)k;
        ap[k] = __expf(coeff * tt * tt);
    }
    int src = eip[2*e], dst = eip[2*e + 1];
    int pc = g_rs[g*(ATN+1) + dst] + atomicAdd(&g_cur[g*ATN + dst], 1);
    g_csrsrc[eofs + pc] = src;
    g_csrw[eofs + pc] = p;
}

__global__ void k_embed(const int* __restrict__ sites, const int* __restrict__ sitesp,
                        const float* __restrict__ embw, const float* __restrict__ embpw){
    int idx = blockIdx.x*blockDim.x + threadIdx.x;
    if(idx >= NN*HD) return;
    int n = idx >> 6, f = idx & 63;
    int b = n / ATN, i = n - b*ATN;
    float v;
    if(i < M1N) v = embw[sites[b*M1N + i]*HD + f];
    else        v = embpw[sitesp[b*M2N + (i - M1N)]*HD + f];
    g_h[idx] = v;
}

__global__ void k_cleanup(){
    int i = blockIdx.x*blockDim.x + threadIdx.x;
    if(i < 3*ATN){ g_cnt[i] = 0; g_cur[i] = 0; }
    if(i < 3*CN){ g_cc[i] = 0; g_ccur[i] = 0; }
}

// ---------------- edge-filter MLP (R8 union-buffer form, measured 113us) ----------------
__global__ void k_wmlp(const float* __restrict__ mw1, const float* __restrict__ mb1,
                       const float* __restrict__ mw2, const float* __restrict__ mb2,
                       int g, int eofs){
    const int c = blockIdx.y, l = blockIdx.z;
    const int cb = g_cbase[g*(CN+1)+c];
    const int ce = g_cbase[g*(CN+1)+c+1];
    const int r0 = cb + blockIdx.x*64;
    if(r0 >= ce) return;
    const int t = threadIdx.x;
    const int tc = t & 15, tr = t >> 4;

    __shared__ __align__(16) float sW[64*64];
    __shared__ __align__(16) float sU[64*65];   // attr tile, then H tile

    const int pgc = (l*3 + g)*CN + c;
    const float* w1 = mw1 + pgc*NGN*HD;
    for(int i = t; i < NGN*HD; i += 128) sW[i] = w1[i];
    for(int i = t; i < 64*NGN; i += 128){
        int rr = i / NGN, kk = i - rr*NGN;
        int row = r0 + rr;
        sU[rr*65 + kk] = (row < ce) ? g_attr[(size_t)(eofs + row)*NGN + kk] : 0.0f;
    }
    __syncthreads();

    float acc[8][4];
    #pragma unroll
    for(int ri = 0; ri < 8; ri++){ acc[ri][0]=0; acc[ri][1]=0; acc[ri][2]=0; acc[ri][3]=0; }
    for(int k = 0; k < NGN; k++){
        float4 w = *(const float4*)&sW[k*64 + tc*4];
        #pragma unroll
        for(int ri = 0; ri < 8; ri++){
            float a = sU[(tr*8 + ri)*65 + k];
            acc[ri][0] += a*w.x; acc[ri][1] += a*w.y;
            acc[ri][2] += a*w.z; acc[ri][3] += a*w.w;
        }
    }
    __syncthreads();      // all reads of sU (attr) and sW (w1) done

    float b1v[4];
    #pragma unroll
    for(int j = 0; j < 4; j++) b1v[j] = mb1[pgc*HD + tc*4 + j];
    #pragma unroll
    for(int ri = 0; ri < 8; ri++)
        #pragma unroll
        for(int j = 0; j < 4; j++)
            sU[(tr*8 + ri)*65 + tc*4 + j] = sspf(acc[ri][j] + b1v[j]);
    const float* w2 = mw2 + pgc*HD*HD;
    for(int i = t; i < HD*HD; i += 128) sW[i] = w2[i];
    __syncthreads();

    float acc2[8][4];
    #pragma unroll
    for(int ri = 0; ri < 8; ri++){ acc2[ri][0]=0; acc2[ri][1]=0; acc2[ri][2]=0; acc2[ri][3]=0; }
    for(int k = 0; k < HD; k++){
        float4 w = *(const float4*)&sW[k*64 + tc*4];
        #pragma unroll
        for(int ri = 0; ri < 8; ri++){
            float a = sU[(tr*8 + ri)*65 + k];
            acc2[ri][0] += a*w.x; acc2[ri][1] += a*w.y;
            acc2[ri][2] += a*w.z; acc2[ri][3] += a*w.w;
        }
    }
    float b2v[4];
    #pragma unroll
    for(int j = 0; j < 4; j++) b2v[j] = mb2[pgc*HD + tc*4 + j];
    #pragma unroll
    for(int ri = 0; ri < 8; ri++){
        int row = r0 + tr*8 + ri;
        if(row < ce){
            float cc = g_ccut[eofs + row];
            float4 o;
            o.x = (acc2[ri][0] + b2v[0]) * cc;
            o.y = (acc2[ri][1] + b2v[1]) * cc;
            o.z = (acc2[ri][2] + b2v[2]) * cc;
            o.w = (acc2[ri][3] + b2v[3]) * cc;
            *(float4*)&g_W[(size_t)(l*ETN + eofs + row)*HD + tc*4] = o;
        }
    }
}

// ---------------- lin1 (R7 per-graph form, part of 766us best) ----------------
__global__ void k_lin1(const float* __restrict__ cw1, int l){
    const int gph = blockIdx.y;
    const int r0 = blockIdx.x * 64;
    const int t = threadIdx.x, tc = t & 15, tr = t >> 4;
    __shared__ __align__(16) float sW[64*64];
    __shared__ float sHt[64*65];
    const float* w = cw1 + (l*3 + gph)*HD*HD;
    for(int i = t; i < HD*HD; i += 128) sW[i] = w[i];
    for(int i = t; i < 64*64; i += 128){
        int rr = i >> 6, kk = i & 63;
        sHt[rr*65 + kk] = g_h[(r0 + rr)*HD + kk];
    }
    __syncthreads();
    float acc[8][4];
    #pragma unroll
    for(int ri = 0; ri < 8; ri++){ acc[ri][0]=0; acc[ri][1]=0; acc[ri][2]=0; acc[ri][3]=0; }
    for(int k = 0; k < HD; k++){
        float4 w4 = *(const float4*)&sW[k*64 + tc*4];
        #pragma unroll
        for(int ri = 0; ri < 8; ri++){
            float a = sHt[(tr*8 + ri)*65 + k];
            acc[ri][0] += a*w4.x; acc[ri][1] += a*w4.y;
            acc[ri][2] += a*w4.z; acc[ri][3] += a*w4.w;
        }
    }
    float* xo = g_x[gph];
    #pragma unroll
    for(int ri = 0; ri < 8; ri++){
        int row = r0 + tr*8 + ri;
        float4 o; o.x = acc[ri][0]; o.y = acc[ri][1]; o.z = acc[ri][2]; o.w = acc[ri][3];
        *(float4*)&xo[row*HD + tc*4] = o;
    }
}

// ---------------- CSR aggregation: 1 warp per dst, u64 lanes ----------------
__global__ void k_agg(int l){
    const int gph = blockIdx.y;
    const int t = threadIdx.x;
    const int f2 = t & 31;
    const int dq = t >> 5;
    const int dst = blockIdx.x*8 + dq;
    const int eofs = (gph == 0) ? 0 : ((gph == 1) ? E1N : (E1N + E2N));
    const int s = g_rs[gph*(ATN+1) + dst];
    const int e = g_rs[gph*(ATN+1) + dst + 1];
    const u64* __restrict__ xq = (const u64*)g_x[gph];
    const u64* __restrict__ Wq = (const u64*)(g_W + (size_t)l*ETN*HD) + (size_t)eofs*32;
    u64 acc[NB];
    #pragma unroll
    for(int b = 0; b < NB; b++) acc[b] = 0ull;
    int src = 0, wp = 0;
    if(s < e){ src = __ldg(&g_csrsrc[eofs + s]); wp = __ldg(&g_csrw[eofs + s]); }
    for(int p = s; p < e; p++){
        int ns = 0, nw = 0;
        if(p + 1 < e){ ns = __ldg(&g_csrsrc[eofs + p + 1]); nw = __ldg(&g_csrw[eofs + p + 1]); }
        u64 w = Wq[(size_t)wp*32 + f2];
        int base = src*32 + f2;
        #pragma unroll
        for(int b = 0; b < NB; b++)
            fma2(acc[b], xq[base + b*ATN*32], w);
        src = ns; wp = nw;
    }
    u64* aq = (u64*)g_agg[gph];
    int ob = dst*32 + f2;
    #pragma unroll
    for(int b = 0; b < NB; b++)
        aq[ob + b*ATN*32] = acc[b];
}

// ---------------- block (R7 32-row form, part of 766us best) ----------------
__global__ void k_block(const float* __restrict__ cw2, const float* __restrict__ cb2,
                        const float* __restrict__ bw, const float* __restrict__ bb,
                        int l){
    const int r0 = blockIdx.x * 32;
    const int t = threadIdx.x, tc = t & 15, tr = t >> 4;
    __shared__ __align__(16) float sW[64*64];
    __shared__ float sAg[32*65];
    __shared__ float sT[32*65];
    float hacc[4][4];
    #pragma unroll
    for(int ri = 0; ri < 4; ri++){ hacc[ri][0]=0; hacc[ri][1]=0; hacc[ri][2]=0; hacc[ri][3]=0; }

    for(int g = 0; g < 3; g++){
        const float* w = cw2 + (l*3 + g)*HD*HD;
        for(int i = t; i < HD*HD; i += 128) sW[i] = w[i];
        const float* ag = g_agg[g];
        for(int i = t; i < 32*64; i += 128){
            int rr = i >> 6, kk = i & 63;
            sAg[rr*65 + kk] = ag[(r0 + rr)*HD + kk];
        }
        __syncthreads();

        float acc[4][4];
        #pragma unroll
        for(int ri = 0; ri < 4; ri++){ acc[ri][0]=0; acc[ri][1]=0; acc[ri][2]=0; acc[ri][3]=0; }
        for(int k = 0; k < HD; k++){
            float4 w4 = *(const float4*)&sW[k*64 + tc*4];
            #pragma unroll
            for(int ri = 0; ri < 4; ri++){
                float a = sAg[(tr*4 + ri)*65 + k];
                acc[ri][0] += a*w4.x; acc[ri][1] += a*w4.y;
                acc[ri][2] += a*w4.z; acc[ri][3] += a*w4.w;
            }
        }
        float b2v[4];
        #pragma unroll
        for(int j = 0; j < 4; j++) b2v[j] = cb2[(l*3 + g)*HD + tc*4 + j];
        #pragma unroll
        for(int ri = 0; ri < 4; ri++)
            #pragma unroll
            for(int j = 0; j < 4; j++)
                sT[(tr*4 + ri)*65 + tc*4 + j] = sspf(acc[ri][j] + b2v[j]);
        __syncthreads();

        const float* w2 = bw + (l*3 + g)*HD*HD;
        for(int i = t; i < HD*HD; i += 128) sW[i] = w2[i];
        __syncthreads();

        for(int k = 0; k < HD; k++){
            float4 w4 = *(const float4*)&sW[k*64 + tc*4];
            #pragma unroll
            for(int ri = 0; ri < 4; ri++){
                float a = sT[(tr*4 + ri)*65 + k];
                hacc[ri][0] += a*w4.x; hacc[ri][1] += a*w4.y;
                hacc[ri][2] += a*w4.z; hacc[ri][3] += a*w4.w;
            }
        }
        float bbv[4];
        #pragma unroll
        for(int j = 0; j < 4; j++) bbv[j] = bb[(l*3 + g)*HD + tc*4 + j];
        #pragma unroll
        for(int ri = 0; ri < 4; ri++)
            #pragma unroll
            for(int j = 0; j < 4; j++) hacc[ri][j] += bbv[j];
        __syncthreads();
    }

    #pragma unroll
    for(int ri = 0; ri < 4; ri++){
        int row = r0 + tr*4 + ri;
        float4* hp = (float4*)&g_h[row*HD + tc*4];
        float4 hv = *hp;
        hv.x += hacc[ri][0]; hv.y += hacc[ri][1];
        hv.z += hacc[ri][2]; hv.w += hacc[ri][3];
        *hp = hv;
    }
}

__global__ void k_readout(const float* __restrict__ ow1, const float* __restrict__ ob1,
                          const float* __restrict__ ow2, const float* __restrict__ ob2,
                          float* __restrict__ out){
    __shared__ float sS[NB*HD];
    __shared__ float sV[NB*32];
    int t = threadIdx.x;
    int b = t >> 6, f = t & 63;
    float s = 0.0f;
    const float* hp = g_h + (size_t)(b*ATN + M1N)*HD + f;
    #pragma unroll 4
    for(int i = 0; i < M2N; i++) s += hp[(size_t)i*HD];
    sS[b*HD + f] = s;
    __syncthreads();
    if(t < NB*32){
        int b2 = t >> 5, j = t & 31;
        float v = 0.0f;
        #pragma unroll 8
        for(int f2 = 0; f2 < HD; f2++) v += sS[b2*HD + f2] * ow1[f2*32 + j];
        sV[b2*32 + j] = v + (float)M2N * ob1[j];
    }
    __syncthreads();
    if(t < NB){
        float o = 0.0f;
        #pragma unroll
        for(int j = 0; j < 32; j++) o += sV[t*32 + j] * ow2[j];
        out[t] = o + (float)M2N * ob2[0];
    }
}

extern "C" void kernel_launch(void* const* d_in, const int* in_sizes, int n_in,
                              void* d_out, int out_size){
    (void)in_sizes; (void)n_in; (void)out_size;
    const int*   sites  = (const int*)d_in[0];
    const int*   sitesp = (const int*)d_in[1];
    const int*   ei1 = (const int*)d_in[2];
    const float* ew1 = (const float*)d_in[3];
    const int*   c1  = (const int*)d_in[4];
    const int*   ei2 = (const int*)d_in[5];
    const float* ew2 = (const float*)d_in[6];
    const int*   c2  = (const int*)d_in[7];
    const int*   ei3 = (const int*)d_in[8];
    const float* ew3 = (const float*)d_in[9];
    const int*   c3  = (const int*)d_in[10];
    const float* embw  = (const float*)d_in[11];
    const float* embpw = (const float*)d_in[12];
    const float* mw1 = (const float*)d_in[13];
    const float* mb1 = (const float*)d_in[14];
    const float* mw2 = (const float*)d_in[15];
    const float* mb2 = (const float*)d_in[16];
    const float* cw1 = (const float*)d_in[17];
    const float* cw2 = (const float*)d_in[18];
    const float* cb2 = (const float*)d_in[19];
    const float* bw  = (const float*)d_in[20];
    const float* bb  = (const float*)d_in[21];
    const float* ow1 = (const float*)d_in[22];
    const float* ob1 = (const float*)d_in[23];
    const float* ow2 = (const float*)d_in[24];
    const float* ob2 = (const float*)d_in[25];
    float* out = (float*)d_out;

    k_count<<<(ETN + 255)/256, 256>>>(ei1, ei2, ei3, c1, c2, c3);               // 1
    k_cbase_rs<<<3, 32>>>();                                                    // 2
    k_fill<<<(ETN + 255)/256, 256>>>(ei1, ei2, ei3, ew1, ew2, ew3, c1, c2, c3); // 3

    dim3 gw0((E1N + 63)/64, CN, LN);
    dim3 gw1((E2N + 63)/64, CN, LN);
    dim3 gw2((E3N + 63)/64, CN, LN);
    k_wmlp<<<gw0, 128>>>(mw1, mb1, mw2, mb2, 0, 0);                             // 4 <- profiled
    k_wmlp<<<gw1, 128>>>(mw1, mb1, mw2, mb2, 1, E1N);
    k_wmlp<<<gw2, 128>>>(mw1, mb1, mw2, mb2, 2, E1N + E2N);
    k_embed<<<(NN*HD + 255)/256, 256>>>(sites, sitesp, embw, embpw);

    for(int l = 0; l < LN; l++){
        k_lin1<<<dim3(NN/64, 3), 128>>>(cw1, l);
        k_agg<<<dim3(ATN/8, 3), 256>>>(l);
        k_block<<<NN/32, 128>>>(cw2, cb2, bw, bb, l);
    }
    k_readout<<<1, 512>>>(ow1, ob1, ow2, ob2, out);
    k_cleanup<<<(3*ATN + 255)/256, 256>>>();
}